// round 5
// baseline (speedup 1.0000x reference)
#include <cuda_runtime.h>
#include <cfloat>
#include <math.h>

#define BB 8
#define NN_PTS 8192
#define CIN 64
#define PP 1024
#define SS 32
#define M_ROWS (BB*PP*SS)   // 262144

// ---------------- scratch (device globals; no allocations) ----------------
__device__ float  g_pts_t[BB*NN_PTS*CIN];     // 16MB  [b][n][64]
__device__ float4 g_xyz4[BB*NN_PTS];          // [b][n] (x,y,z,|x|^2)
__device__ int    g_fps[BB*PP];
__device__ float4 g_newxyz4[BB*PP];
__device__ int    g_knn[BB*PP*SS];
__device__ float  g_h1[(size_t)M_ROWS*64];    // 64MB
__device__ float  g_h2[(size_t)M_ROWS*64];    // 64MB
__device__ float  g_max3[BB*PP*128];
__device__ float  g_min3[BB*PP*128];
__device__ double g_sum[256];
__device__ double g_sumsq[256];
__device__ float  g_aff_a[256];
__device__ float  g_aff_c[256];

// ---------------- tiny utility kernels ----------------
__global__ void zero_stats_kernel() {
    int i = threadIdx.x;
    if (i < 256) { g_sum[i] = 0.0; g_sumsq[i] = 0.0; }
}

// points [B][64][N] -> g_pts_t [B][N][64]
__global__ void transpose_pts_kernel(const float* __restrict__ pts) {
    int n = blockIdx.x * blockDim.x + threadIdx.x;
    if (n >= BB*NN_PTS) return;
    int b = n >> 13, nn = n & (NN_PTS-1);
    const float* src = pts + (size_t)b*64*NN_PTS + nn;
    float4* dst = reinterpret_cast<float4*>(g_pts_t + (size_t)n*64);
    #pragma unroll
    for (int c4 = 0; c4 < 16; c4++) {
        float4 v;
        v.x = src[(size_t)(c4*4+0)*NN_PTS];
        v.y = src[(size_t)(c4*4+1)*NN_PTS];
        v.z = src[(size_t)(c4*4+2)*NN_PTS];
        v.w = src[(size_t)(c4*4+3)*NN_PTS];
        dst[c4] = v;
    }
}

// xyz [B][3][N] -> g_xyz4 [B][N] with precomputed |x|^2
// FMA-contracted square-reduce: fma(z,z, fma(y,y, x*x)) — XLA fused emitter style.
__global__ void make_xyz4_kernel(const float* __restrict__ xyz) {
    int i = blockIdx.x * blockDim.x + threadIdx.x;
    if (i >= BB*NN_PTS) return;
    int b = i >> 13, nn = i & (NN_PTS-1);
    float x = xyz[((size_t)b*3+0)*NN_PTS + nn];
    float y = xyz[((size_t)b*3+1)*NN_PTS + nn];
    float z = xyz[((size_t)b*3+2)*NN_PTS + nn];
    float x2 = __fmaf_rn(z, z, __fmaf_rn(y, y, __fmul_rn(x, x)));
    g_xyz4[i] = make_float4(x, y, z, x2);
}

// ---------------- FPS: 1 block per batch, 1024 threads ----------------
// Distance update FMA-contracted to match the same emitter hypothesis.
__global__ void fps_kernel(float* __restrict__ d_out) {
    const int b = blockIdx.x;
    const int tid = threadIdx.x;
    const float4* X = g_xyz4 + (size_t)b*NN_PTS;

    float px[8], py[8], pz[8], dist[8];
    #pragma unroll
    for (int j = 0; j < 8; j++) {
        float4 v = X[tid*8+j];
        px[j] = v.x; py[j] = v.y; pz[j] = v.z;
        dist[j] = 1e10f;
    }

    __shared__ float sval[32];
    __shared__ int   sidx[32];
    __shared__ int   s_far;

    int far = 0;
    for (int it = 0; it < PP; it++) {
        if (tid == 0) {
            g_fps[b*PP + it] = far;
            float4 c = X[far];
            g_newxyz4[b*PP + it] = c;
            d_out[((size_t)b*3+0)*PP + it] = c.x;
            d_out[((size_t)b*3+1)*PP + it] = c.y;
            d_out[((size_t)b*3+2)*PP + it] = c.z;
        }
        float4 c = X[far];  // uniform broadcast load
        float bestv = -1.0f; int besti = 0;
        #pragma unroll
        for (int j = 0; j < 8; j++) {
            float dx = __fsub_rn(px[j], c.x);
            float dy = __fsub_rn(py[j], c.y);
            float dz = __fsub_rn(pz[j], c.z);
            float d = __fmaf_rn(dz, dz, __fmaf_rn(dy, dy, __fmul_rn(dx, dx)));
            dist[j] = fminf(dist[j], d);
            if (dist[j] > bestv) { bestv = dist[j]; besti = tid*8 + j; }
        }
        #pragma unroll
        for (int o = 16; o; o >>= 1) {
            float ov = __shfl_down_sync(0xffffffffu, bestv, o);
            int   oi = __shfl_down_sync(0xffffffffu, besti, o);
            if (ov > bestv || (ov == bestv && oi < besti)) { bestv = ov; besti = oi; }
        }
        if ((tid & 31) == 0) { sval[tid>>5] = bestv; sidx[tid>>5] = besti; }
        __syncthreads();
        if (tid < 32) {
            bestv = sval[tid]; besti = sidx[tid];
            #pragma unroll
            for (int o = 16; o; o >>= 1) {
                float ov = __shfl_down_sync(0xffffffffu, bestv, o);
                int   oi = __shfl_down_sync(0xffffffffu, besti, o);
                if (ov > bestv || (ov == bestv && oi < besti)) { bestv = ov; besti = oi; }
            }
            if (tid == 0) s_far = besti;
        }
        __syncthreads();
        far = s_far;
    }
}

// ---------------- KNN: thread per centroid, shared xyz tiles ----------------
// Key = fp32 d2 exactly as the reference computes it (hypothesized):
//   p2,c2 = FMA-contracted square-reduce; dot = ascending-k GEMM FMA chain;
//   d2 = (p2 - 2*dot) + c2 with plain rounds (2*dot exact).
// Exact ties resolved toward the LOWER index (top_k semantics).
__global__ void knn_kernel() {
    extern __shared__ char sm_raw[];
    float4* tile = reinterpret_cast<float4*>(sm_raw);                 // 2048 float4 = 32KB
    float*  lv   = reinterpret_cast<float*>(sm_raw + 2048*16);        // [32][128] = 16KB
    int*    li   = reinterpret_cast<int*>(sm_raw + 2048*16 + 32*128*4); // 16KB

    const int b = blockIdx.y;
    const int tid = threadIdx.x;
    const int p = blockIdx.x*128 + tid;

    float4 q = g_newxyz4[b*PP + p];
    const float p2 = q.w;

    #pragma unroll
    for (int s = 0; s < SS; s++) { lv[s*128+tid] = FLT_MAX; li[s*128+tid] = 0x7fffffff; }
    float worst = FLT_MAX; int wslot = 0; int widx = 0x7fffffff;

    const float4* X = g_xyz4 + (size_t)b*NN_PTS;
    for (int t0 = 0; t0 < NN_PTS; t0 += 2048) {
        __syncthreads();
        for (int j = tid; j < 2048; j += 128) tile[j] = X[t0 + j];
        __syncthreads();
        #pragma unroll 4
        for (int j = 0; j < 2048; j++) {
            float4 v = tile[j];
            float dot = __fmaf_rn(q.z, v.z, __fmaf_rn(q.y, v.y, __fmul_rn(q.x, v.x)));
            float d2 = __fadd_rn(__fsub_rn(p2, __fmul_rn(2.0f, dot)), v.w);
            if (d2 < worst || (d2 == worst && (t0 + j) < widx)) {
                lv[wslot*128+tid] = d2; li[wslot*128+tid] = t0 + j;
                float mw = -FLT_MAX; int ms = 0; int mi = -1;
                #pragma unroll
                for (int s = 0; s < SS; s++) {
                    float vv = lv[s*128+tid]; int ii = li[s*128+tid];
                    if (vv > mw || (vv == mw && ii > mi)) { mw = vv; ms = s; mi = ii; }
                }
                worst = mw; wslot = ms; widx = mi;
            }
        }
    }
    #pragma unroll
    for (int s = 0; s < SS; s++) g_knn[((size_t)(b*PP + p))*SS + s] = li[s*128+tid];
}

// ---------------- conv layers: 128x64 block tile, 8x8 thread tile ----------------
// Exact fp32; per-output single-accumulator ascending-k FMA chain.
template<int K, int LAYER>
__global__ void conv_kernel(const float* __restrict__ W, const float* __restrict__ bias) {
    extern __shared__ float sm[];
    float* A_s = sm;              // [K][128]
    float* W_s = sm + K*128;      // [K][64]
    const int tid = threadIdx.x;
    const int rowBase = blockIdx.x * 128;
    const int colBase = blockIdx.y * 64;

    for (int i = tid; i < K*64; i += 128) {
        int k = i >> 6, o = i & 63;
        W_s[i] = W[(size_t)(colBase + o)*K + k];
    }
    {
        int r = rowBase + tid;
        if constexpr (LAYER == 1) {
            int b = r >> 15, rem = r & 32767, p = rem >> 5;
            int idx = g_knn[r];
            float4 nq = g_newxyz4[(b<<10) + p];
            float4 g  = g_xyz4[(b<<13) + idx];
            A_s[0*128+tid] = __fsub_rn(g.x, nq.x);
            A_s[1*128+tid] = __fsub_rn(g.y, nq.y);
            A_s[2*128+tid] = __fsub_rn(g.z, nq.z);
            const float4* prow = reinterpret_cast<const float4*>(g_pts_t + ((size_t)(b<<13) + idx)*64);
            #pragma unroll
            for (int c4 = 0; c4 < 16; c4++) {
                float4 v = prow[c4];
                int c = 3 + c4*4;
                A_s[(c+0)*128+tid] = v.x;
                A_s[(c+1)*128+tid] = v.y;
                A_s[(c+2)*128+tid] = v.z;
                A_s[(c+3)*128+tid] = v.w;
            }
        } else {
            const float* hin = (LAYER == 2) ? g_h1 : g_h2;
            const int off = (LAYER == 2) ? 0 : 64;
            const float4* hrow = reinterpret_cast<const float4*>(hin + (size_t)r*64);
            #pragma unroll
            for (int c4 = 0; c4 < 16; c4++) {
                float4 v = hrow[c4];
                int c = c4*4;
                A_s[(c+0)*128+tid] = fmaxf(fmaf(v.x, g_aff_a[off+c+0], g_aff_c[off+c+0]), 0.0f);
                A_s[(c+1)*128+tid] = fmaxf(fmaf(v.y, g_aff_a[off+c+1], g_aff_c[off+c+1]), 0.0f);
                A_s[(c+2)*128+tid] = fmaxf(fmaf(v.z, g_aff_a[off+c+2], g_aff_c[off+c+2]), 0.0f);
                A_s[(c+3)*128+tid] = fmaxf(fmaf(v.w, g_aff_a[off+c+3], g_aff_c[off+c+3]), 0.0f);
            }
        }
    }
    __syncthreads();

    const int rg = tid >> 3, cg = tid & 7;
    float acc[8][8];
    #pragma unroll
    for (int i = 0; i < 8; i++)
        #pragma unroll
        for (int j = 0; j < 8; j++) acc[i][j] = 0.0f;

    #pragma unroll 4
    for (int k = 0; k < K; k++) {
        float4 a0 = *reinterpret_cast<const float4*>(&A_s[k*128 + rg*8]);
        float4 a1 = *reinterpret_cast<const float4*>(&A_s[k*128 + rg*8 + 4]);
        float4 w0 = *reinterpret_cast<const float4*>(&W_s[k*64 + cg*8]);
        float4 w1 = *reinterpret_cast<const float4*>(&W_s[k*64 + cg*8 + 4]);
        float av[8] = {a0.x,a0.y,a0.z,a0.w,a1.x,a1.y,a1.z,a1.w};
        float wv[8] = {w0.x,w0.y,w0.z,w0.w,w1.x,w1.y,w1.z,w1.w};
        #pragma unroll
        for (int i = 0; i < 8; i++)
            #pragma unroll
            for (int j = 0; j < 8; j++)
                acc[i][j] = __fmaf_rn(av[i], wv[j], acc[i][j]);
    }

    float bb[8];
    #pragma unroll
    for (int j = 0; j < 8; j++) bb[j] = bias[colBase + cg*8 + j];
    #pragma unroll
    for (int i = 0; i < 8; i++)
        #pragma unroll
        for (int j = 0; j < 8; j++) acc[i][j] = __fadd_rn(acc[i][j], bb[j]);

    float cs[8], cq[8];
    #pragma unroll
    for (int j = 0; j < 8; j++) { cs[j] = 0.0f; cq[j] = 0.0f; }
    #pragma unroll
    for (int i = 0; i < 8; i++)
        #pragma unroll
        for (int j = 0; j < 8; j++) { cs[j] += acc[i][j]; cq[j] += acc[i][j]*acc[i][j]; }

    __syncthreads();   // done reading A_s/W_s — reuse as reduction space
    float* red = A_s;
    #pragma unroll
    for (int j = 0; j < 8; j++) {
        red[rg*64 + cg*8 + j] = cs[j];
        red[1024 + rg*64 + cg*8 + j] = cq[j];
    }
    if constexpr (LAYER == 3) {
        float tmx[8], tmn[8];
        #pragma unroll
        for (int j = 0; j < 8; j++) { tmx[j] = -FLT_MAX; tmn[j] = FLT_MAX; }
        #pragma unroll
        for (int i = 0; i < 8; i++)
            #pragma unroll
            for (int j = 0; j < 8; j++) { tmx[j] = fmaxf(tmx[j], acc[i][j]); tmn[j] = fminf(tmn[j], acc[i][j]); }
        #pragma unroll
        for (int j = 0; j < 8; j++) {
            red[2048 + rg*64 + cg*8 + j] = tmx[j];
            red[3072 + rg*64 + cg*8 + j] = tmn[j];
        }
    }
    __syncthreads();

    if (tid < 64) {
        float s = 0.0f, s2 = 0.0f;
        #pragma unroll
        for (int r2 = 0; r2 < 16; r2++) { s += red[r2*64 + tid]; s2 += red[1024 + r2*64 + tid]; }
        const int statsOff = (LAYER == 1) ? 0 : ((LAYER == 2) ? 64 : 128);
        atomicAdd(&g_sum[statsOff + colBase + tid], (double)s);
        atomicAdd(&g_sumsq[statsOff + colBase + tid], (double)s2);
    }

    if constexpr (LAYER < 3) {
        float* hout = (LAYER == 1) ? g_h1 : g_h2;
        #pragma unroll
        for (int i = 0; i < 8; i++) {
            float4 v0 = make_float4(acc[i][0], acc[i][1], acc[i][2], acc[i][3]);
            float4 v1 = make_float4(acc[i][4], acc[i][5], acc[i][6], acc[i][7]);
            float4* dst = reinterpret_cast<float4*>(hout + (size_t)(rowBase + rg*8 + i)*64 + cg*8);
            dst[0] = v0; dst[1] = v1;
        }
    } else {
        #pragma unroll
        for (int t = 0; t < 2; t++) {
            int o = tid*2 + t;
            int gi = o >> 6, c = o & 63;
            float mx = -FLT_MAX, mn = FLT_MAX;
            #pragma unroll
            for (int rr = 0; rr < 4; rr++) {
                mx = fmaxf(mx, red[2048 + (gi*4+rr)*64 + c]);
                mn = fminf(mn, red[3072 + (gi*4+rr)*64 + c]);
            }
            int gp = (rowBase >> 5) + gi;   // global (b*P + p)
            g_max3[(size_t)gp*128 + colBase + c] = mx;
            g_min3[(size_t)gp*128 + colBase + c] = mn;
        }
    }
}

// ---------------- BN finalize ----------------
__global__ void finalize_bn_kernel(const float* __restrict__ g, const float* __restrict__ bt,
                                   int off, int nc) {
    int c = blockIdx.x*blockDim.x + threadIdx.x;
    if (c < nc) {
        double m = g_sum[off+c] * (1.0 / (double)M_ROWS);
        double v = g_sumsq[off+c] * (1.0 / (double)M_ROWS) - m*m;
        float a = g[c] * rsqrtf(fmaxf((float)v, 0.0f) + 1e-5f);
        g_aff_a[off+c] = a;
        g_aff_c[off+c] = (float)((double)bt[c] - m * (double)a);
    }
}

// ---------------- final output: BN3 via max/min-by-sign, layout [B][128][P] ----------------
__global__ void writeout_kernel(float* __restrict__ out) {
    int i = blockIdx.x*256 + threadIdx.x;   // over B*128*P = 1048576
    int p = i & 1023, c = (i >> 10) & 127, b = i >> 17;
    float a = g_aff_a[128 + c], cc = g_aff_c[128 + c];
    float x = (a >= 0.0f) ? g_max3[(size_t)((b<<10)+p)*128 + c]
                          : g_min3[(size_t)((b<<10)+p)*128 + c];
    out[24576 + i] = fmaf(x, a, cc);
}

// ---------------- launch ----------------
extern "C" void kernel_launch(void* const* d_in, const int* in_sizes, int n_in,
                              void* d_out, int out_size) {
    (void)in_sizes; (void)n_in; (void)out_size;
    const float* xyz = (const float*)d_in[0];
    const float* pts = (const float*)d_in[1];
    const float* w1  = (const float*)d_in[2];
    const float* b1  = (const float*)d_in[3];
    const float* g1  = (const float*)d_in[4];
    const float* bt1 = (const float*)d_in[5];
    const float* w2  = (const float*)d_in[6];
    const float* b2  = (const float*)d_in[7];
    const float* g2  = (const float*)d_in[8];
    const float* bt2 = (const float*)d_in[9];
    const float* w3  = (const float*)d_in[10];
    const float* b3  = (const float*)d_in[11];
    const float* g3  = (const float*)d_in[12];
    const float* bt3 = (const float*)d_in[13];
    float* out = (float*)d_out;

    const int knn_smem = 2048*16 + 32*128*4 + 32*128*4;  // 65536
    cudaFuncSetAttribute(knn_kernel, cudaFuncAttributeMaxDynamicSharedMemorySize, knn_smem);
    cudaFuncSetAttribute(conv_kernel<67,1>, cudaFuncAttributeMaxDynamicSharedMemorySize, (67*128 + 67*64)*4);
    cudaFuncSetAttribute(conv_kernel<64,2>, cudaFuncAttributeMaxDynamicSharedMemorySize, 49152);
    cudaFuncSetAttribute(conv_kernel<64,3>, cudaFuncAttributeMaxDynamicSharedMemorySize, 49152);

    zero_stats_kernel<<<1, 256>>>();
    transpose_pts_kernel<<<(BB*NN_PTS)/256, 256>>>(pts);
    make_xyz4_kernel<<<(BB*NN_PTS)/256, 256>>>(xyz);
    fps_kernel<<<BB, 1024>>>(out);
    knn_kernel<<<dim3(PP/128, BB), 128, knn_smem>>>();
    conv_kernel<67,1><<<dim3(M_ROWS/128, 1), 128, (67*128 + 67*64)*4>>>(w1, b1);
    finalize_bn_kernel<<<1, 64>>>(g1, bt1, 0, 64);
    conv_kernel<64,2><<<dim3(M_ROWS/128, 1), 128, 49152>>>(w2, b2);
    finalize_bn_kernel<<<1, 64>>>(g2, bt2, 64, 64);
    conv_kernel<64,3><<<dim3(M_ROWS/128, 2), 128, 49152>>>(w3, b3);
    finalize_bn_kernel<<<1, 128>>>(g3, bt3, 128, 128);
    writeout_kernel<<<(BB*128*PP)/256, 256>>>(out);
}

// round 6
// speedup vs baseline: 1.1445x; 1.1445x over previous
#include <cuda_runtime.h>
#include <cfloat>
#include <math.h>

#define BB 8
#define NN_PTS 8192
#define CIN 64
#define PP 1024
#define SS 32
#define M_ROWS (BB*PP*SS)   // 262144

typedef unsigned long long u64;

// ---------------- packed f32x2 helpers (each lane = exact scalar fp32 op) ----------------
__device__ __forceinline__ u64 f2_pack(float a, float b) {
    u64 r; asm("mov.b64 %0, {%1, %2};" : "=l"(r) : "f"(a), "f"(b)); return r;
}
__device__ __forceinline__ void f2_unpack(float& a, float& b, u64 v) {
    asm("mov.b64 {%0, %1}, %2;" : "=f"(a), "=f"(b) : "l"(v));
}
__device__ __forceinline__ u64 f2_add(u64 a, u64 b) {
    u64 r; asm("add.rn.f32x2 %0, %1, %2;" : "=l"(r) : "l"(a), "l"(b)); return r;
}
__device__ __forceinline__ u64 f2_mul(u64 a, u64 b) {
    u64 r; asm("mul.rn.f32x2 %0, %1, %2;" : "=l"(r) : "l"(a), "l"(b)); return r;
}
__device__ __forceinline__ u64 f2_fma(u64 a, u64 b, u64 c) {
    u64 r; asm("fma.rn.f32x2 %0, %1, %2, %3;" : "=l"(r) : "l"(a), "l"(b), "l"(c)); return r;
}

// ---------------- scratch (device globals; no allocations) ----------------
__device__ float  g_pts_t[BB*NN_PTS*CIN];     // 16MB  [b][n][64]
__device__ float4 g_xyz4[BB*NN_PTS];          // [b][n] (x,y,z,|x|^2)
__device__ float4 g_newxyz4[BB*PP];
__device__ int    g_knn[BB*PP*SS];
__device__ float  g_h1[(size_t)M_ROWS*64];    // 64MB
__device__ float  g_h2[(size_t)M_ROWS*64];    // 64MB
__device__ float  g_max3[BB*PP*128];
__device__ float  g_min3[BB*PP*128];
__device__ double g_sum[256];
__device__ double g_sumsq[256];
__device__ float  g_aff_a[256];
__device__ float  g_aff_c[256];

// ---------------- tiny utility kernels ----------------
__global__ void zero_stats_kernel() {
    int i = threadIdx.x;
    if (i < 256) { g_sum[i] = 0.0; g_sumsq[i] = 0.0; }
}

// points [B][64][N] -> g_pts_t [B][N][64]
__global__ void transpose_pts_kernel(const float* __restrict__ pts) {
    int n = blockIdx.x * blockDim.x + threadIdx.x;
    if (n >= BB*NN_PTS) return;
    int b = n >> 13, nn = n & (NN_PTS-1);
    const float* src = pts + (size_t)b*64*NN_PTS + nn;
    float4* dst = reinterpret_cast<float4*>(g_pts_t + (size_t)n*64);
    #pragma unroll
    for (int c4 = 0; c4 < 16; c4++) {
        float4 v;
        v.x = src[(size_t)(c4*4+0)*NN_PTS];
        v.y = src[(size_t)(c4*4+1)*NN_PTS];
        v.z = src[(size_t)(c4*4+2)*NN_PTS];
        v.w = src[(size_t)(c4*4+3)*NN_PTS];
        dst[c4] = v;
    }
}

// xyz [B][3][N] -> g_xyz4 [B][N] with precomputed |x|^2
// FMA-contracted square-reduce: fma(z,z, fma(y,y, x*x)) — matches reference emitter (BIT-EXACT, do not change)
__global__ void make_xyz4_kernel(const float* __restrict__ xyz) {
    int i = blockIdx.x * blockDim.x + threadIdx.x;
    if (i >= BB*NN_PTS) return;
    int b = i >> 13, nn = i & (NN_PTS-1);
    float x = xyz[((size_t)b*3+0)*NN_PTS + nn];
    float y = xyz[((size_t)b*3+1)*NN_PTS + nn];
    float z = xyz[((size_t)b*3+2)*NN_PTS + nn];
    float x2 = __fmaf_rn(z, z, __fmaf_rn(y, y, __fmul_rn(x, x)));
    g_xyz4[i] = make_float4(x, y, z, x2);
}

// ---------------- FPS: 1 block per batch, 1024 threads ----------------
// f32x2-packed distance update (per-lane rounding identical to scalar FFMA) +
// REDUX-based argmax with first-index tie semantics (lane/warp order = ascending idx).
__global__ void fps_kernel(float* __restrict__ d_out) {
    const int b = blockIdx.x;
    const int tid = threadIdx.x;
    const float4* X = g_xyz4 + (size_t)b*NN_PTS;

    u64 px2[4], py2[4], pz2[4];
    float dist[8];
    #pragma unroll
    for (int pr = 0; pr < 4; pr++) {
        float4 v0 = X[tid*8 + 2*pr];
        float4 v1 = X[tid*8 + 2*pr + 1];
        px2[pr] = f2_pack(v0.x, v1.x);
        py2[pr] = f2_pack(v0.y, v1.y);
        pz2[pr] = f2_pack(v0.z, v1.z);
        dist[2*pr] = 1e10f; dist[2*pr+1] = 1e10f;
    }

    __shared__ unsigned swv[32];
    __shared__ int      swi[32];
    __shared__ int      s_far;
    const int lane = tid & 31, wrp = tid >> 5;

    int far = 0;
    for (int it = 0; it < PP; it++) {
        float4 c = X[far];   // uniform broadcast load
        if (tid == 0) {
            g_newxyz4[b*PP + it] = c;
            d_out[((size_t)b*3+0)*PP + it] = c.x;
            d_out[((size_t)b*3+1)*PP + it] = c.y;
            d_out[((size_t)b*3+2)*PP + it] = c.z;
        }
        // (p - c) computed as p + (-c): negation exact, identical rounding
        u64 ncx = f2_pack(-c.x, -c.x);
        u64 ncy = f2_pack(-c.y, -c.y);
        u64 ncz = f2_pack(-c.z, -c.z);

        float bestv = -1.0f; int besti = 0;
        #pragma unroll
        for (int pr = 0; pr < 4; pr++) {
            u64 dx = f2_add(px2[pr], ncx);
            u64 dy = f2_add(py2[pr], ncy);
            u64 dz = f2_add(pz2[pr], ncz);
            u64 s  = f2_fma(dz, dz, f2_fma(dy, dy, f2_mul(dx, dx)));
            float d0, d1; f2_unpack(d0, d1, s);
            dist[2*pr] = fminf(dist[2*pr], d0);
            if (dist[2*pr] > bestv)   { bestv = dist[2*pr];   besti = tid*8 + 2*pr; }
            dist[2*pr+1] = fminf(dist[2*pr+1], d1);
            if (dist[2*pr+1] > bestv) { bestv = dist[2*pr+1]; besti = tid*8 + 2*pr + 1; }
        }

        // warp argmax: uint order == float order for nonneg floats; lowest lane = lowest idx
        unsigned u  = __float_as_uint(bestv);
        unsigned wm = __reduce_max_sync(0xffffffffu, u);
        unsigned bl = __ballot_sync(0xffffffffu, u == wm);
        int wi = __shfl_sync(0xffffffffu, besti, __ffs(bl) - 1);
        if (lane == 0) { swv[wrp] = wm; swi[wrp] = wi; }
        __syncthreads();
        if (tid < 32) {
            unsigned u2 = swv[tid]; int i2 = swi[tid];
            unsigned m2 = __reduce_max_sync(0xffffffffu, u2);
            unsigned b2 = __ballot_sync(0xffffffffu, u2 == m2);
            int fi = __shfl_sync(0xffffffffu, i2, __ffs(b2) - 1);
            if (tid == 0) s_far = fi;
        }
        __syncthreads();
        far = s_far;
    }
}

// ---------------- KNN: thread per centroid, shared xyz tiles (BIT-EXACT selection math) ----
__global__ void knn_kernel() {
    extern __shared__ char sm_raw[];
    float4* tile = reinterpret_cast<float4*>(sm_raw);                 // 2048 float4 = 32KB
    float*  lv   = reinterpret_cast<float*>(sm_raw + 2048*16);        // [32][128] = 16KB
    int*    li   = reinterpret_cast<int*>(sm_raw + 2048*16 + 32*128*4); // 16KB

    const int b = blockIdx.y;
    const int tid = threadIdx.x;
    const int p = blockIdx.x*128 + tid;

    float4 q = g_newxyz4[b*PP + p];
    const float p2 = q.w;

    #pragma unroll
    for (int s = 0; s < SS; s++) { lv[s*128+tid] = FLT_MAX; li[s*128+tid] = 0x7fffffff; }
    float worst = FLT_MAX; int wslot = 0; int widx = 0x7fffffff;

    const float4* X = g_xyz4 + (size_t)b*NN_PTS;
    for (int t0 = 0; t0 < NN_PTS; t0 += 2048) {
        __syncthreads();
        for (int j = tid; j < 2048; j += 128) tile[j] = X[t0 + j];
        __syncthreads();
        #pragma unroll 4
        for (int j = 0; j < 2048; j++) {
            float4 v = tile[j];
            float dot = __fmaf_rn(q.z, v.z, __fmaf_rn(q.y, v.y, __fmul_rn(q.x, v.x)));
            float d2 = __fadd_rn(__fsub_rn(p2, __fmul_rn(2.0f, dot)), v.w);
            if (d2 < worst || (d2 == worst && (t0 + j) < widx)) {
                lv[wslot*128+tid] = d2; li[wslot*128+tid] = t0 + j;
                float mw = -FLT_MAX; int ms = 0; int mi = -1;
                #pragma unroll
                for (int s = 0; s < SS; s++) {
                    float vv = lv[s*128+tid]; int ii = li[s*128+tid];
                    if (vv > mw || (vv == mw && ii > mi)) { mw = vv; ms = s; mi = ii; }
                }
                worst = mw; wslot = ms; widx = mi;
            }
        }
    }
    #pragma unroll
    for (int s = 0; s < SS; s++) g_knn[((size_t)(b*PP + p))*SS + s] = li[s*128+tid];
}

// ---------------- conv layers: 128x64 block tile, 8x8 thread tile, f32x2 mainloop --------
// Exact fp32; per-output single-accumulator ascending-k FMA chain (bit-identical to scalar).
template<int K, int LAYER>
__global__ void conv_kernel(const float* __restrict__ W, const float* __restrict__ bias) {
    extern __shared__ float sm[];
    float* A_s = sm;              // [K][128]
    float* W_s = sm + K*128;      // [K][64]
    const int tid = threadIdx.x;
    const int rowBase = blockIdx.x * 128;
    const int colBase = blockIdx.y * 64;

    for (int i = tid; i < K*64; i += 128) {
        int k = i >> 6, o = i & 63;
        W_s[i] = W[(size_t)(colBase + o)*K + k];
    }
    {
        int r = rowBase + tid;
        if constexpr (LAYER == 1) {
            int b = r >> 15, rem = r & 32767, p = rem >> 5;
            int idx = g_knn[r];
            float4 nq = g_newxyz4[(b<<10) + p];
            float4 g  = g_xyz4[(b<<13) + idx];
            A_s[0*128+tid] = __fsub_rn(g.x, nq.x);
            A_s[1*128+tid] = __fsub_rn(g.y, nq.y);
            A_s[2*128+tid] = __fsub_rn(g.z, nq.z);
            const float4* prow = reinterpret_cast<const float4*>(g_pts_t + ((size_t)(b<<13) + idx)*64);
            #pragma unroll
            for (int c4 = 0; c4 < 16; c4++) {
                float4 v = prow[c4];
                int c = 3 + c4*4;
                A_s[(c+0)*128+tid] = v.x;
                A_s[(c+1)*128+tid] = v.y;
                A_s[(c+2)*128+tid] = v.z;
                A_s[(c+3)*128+tid] = v.w;
            }
        } else {
            const float* hin = (LAYER == 2) ? g_h1 : g_h2;
            const int off = (LAYER == 2) ? 0 : 64;
            const float4* hrow = reinterpret_cast<const float4*>(hin + (size_t)r*64);
            #pragma unroll
            for (int c4 = 0; c4 < 16; c4++) {
                float4 v = hrow[c4];
                int c = c4*4;
                A_s[(c+0)*128+tid] = fmaxf(fmaf(v.x, g_aff_a[off+c+0], g_aff_c[off+c+0]), 0.0f);
                A_s[(c+1)*128+tid] = fmaxf(fmaf(v.y, g_aff_a[off+c+1], g_aff_c[off+c+1]), 0.0f);
                A_s[(c+2)*128+tid] = fmaxf(fmaf(v.z, g_aff_a[off+c+2], g_aff_c[off+c+2]), 0.0f);
                A_s[(c+3)*128+tid] = fmaxf(fmaf(v.w, g_aff_a[off+c+3], g_aff_c[off+c+3]), 0.0f);
            }
        }
    }
    __syncthreads();

    const int rg = tid >> 3, cg = tid & 7;
    u64 acc2[8][4];
    #pragma unroll
    for (int i = 0; i < 8; i++)
        #pragma unroll
        for (int jj = 0; jj < 4; jj++) acc2[i][jj] = 0ull;   // two packed +0.0f

    #pragma unroll 4
    for (int k = 0; k < K; k++) {
        float4 a0 = *reinterpret_cast<const float4*>(&A_s[k*128 + rg*8]);
        float4 a1 = *reinterpret_cast<const float4*>(&A_s[k*128 + rg*8 + 4]);
        ulonglong2 wA = *reinterpret_cast<const ulonglong2*>(&W_s[k*64 + cg*8]);
        ulonglong2 wB = *reinterpret_cast<const ulonglong2*>(&W_s[k*64 + cg*8 + 4]);
        u64 wv2[4] = {wA.x, wA.y, wB.x, wB.y};
        float av[8] = {a0.x,a0.y,a0.z,a0.w,a1.x,a1.y,a1.z,a1.w};
        #pragma unroll
        for (int i = 0; i < 8; i++) {
            u64 ad = f2_pack(av[i], av[i]);
            #pragma unroll
            for (int jj = 0; jj < 4; jj++)
                acc2[i][jj] = f2_fma(ad, wv2[jj], acc2[i][jj]);
        }
    }

    float acc[8][8];
    #pragma unroll
    for (int i = 0; i < 8; i++)
        #pragma unroll
        for (int jj = 0; jj < 4; jj++)
            f2_unpack(acc[i][2*jj], acc[i][2*jj+1], acc2[i][jj]);

    float bb[8];
    #pragma unroll
    for (int j = 0; j < 8; j++) bb[j] = bias[colBase + cg*8 + j];
    #pragma unroll
    for (int i = 0; i < 8; i++)
        #pragma unroll
        for (int j = 0; j < 8; j++) acc[i][j] = __fadd_rn(acc[i][j], bb[j]);

    float cs[8], cq[8];
    #pragma unroll
    for (int j = 0; j < 8; j++) { cs[j] = 0.0f; cq[j] = 0.0f; }
    #pragma unroll
    for (int i = 0; i < 8; i++)
        #pragma unroll
        for (int j = 0; j < 8; j++) { cs[j] += acc[i][j]; cq[j] += acc[i][j]*acc[i][j]; }

    __syncthreads();   // done reading A_s/W_s — reuse as reduction space
    float* red = A_s;
    #pragma unroll
    for (int j = 0; j < 8; j++) {
        red[rg*64 + cg*8 + j] = cs[j];
        red[1024 + rg*64 + cg*8 + j] = cq[j];
    }
    if constexpr (LAYER == 3) {
        float tmx[8], tmn[8];
        #pragma unroll
        for (int j = 0; j < 8; j++) { tmx[j] = -FLT_MAX; tmn[j] = FLT_MAX; }
        #pragma unroll
        for (int i = 0; i < 8; i++)
            #pragma unroll
            for (int j = 0; j < 8; j++) { tmx[j] = fmaxf(tmx[j], acc[i][j]); tmn[j] = fminf(tmn[j], acc[i][j]); }
        #pragma unroll
        for (int j = 0; j < 8; j++) {
            red[2048 + rg*64 + cg*8 + j] = tmx[j];
            red[3072 + rg*64 + cg*8 + j] = tmn[j];
        }
    }
    __syncthreads();

    if (tid < 64) {
        float s = 0.0f, s2 = 0.0f;
        #pragma unroll
        for (int r2 = 0; r2 < 16; r2++) { s += red[r2*64 + tid]; s2 += red[1024 + r2*64 + tid]; }
        const int statsOff = (LAYER == 1) ? 0 : ((LAYER == 2) ? 64 : 128);
        atomicAdd(&g_sum[statsOff + colBase + tid], (double)s);
        atomicAdd(&g_sumsq[statsOff + colBase + tid], (double)s2);
    }

    if constexpr (LAYER < 3) {
        float* hout = (LAYER == 1) ? g_h1 : g_h2;
        #pragma unroll
        for (int i = 0; i < 8; i++) {
            float4 v0 = make_float4(acc[i][0], acc[i][1], acc[i][2], acc[i][3]);
            float4 v1 = make_float4(acc[i][4], acc[i][5], acc[i][6], acc[i][7]);
            float4* dst = reinterpret_cast<float4*>(hout + (size_t)(rowBase + rg*8 + i)*64 + cg*8);
            dst[0] = v0; dst[1] = v1;
        }
    } else {
        #pragma unroll
        for (int t = 0; t < 2; t++) {
            int o = tid*2 + t;
            int gi = o >> 6, c = o & 63;
            float mx = -FLT_MAX, mn = FLT_MAX;
            #pragma unroll
            for (int rr = 0; rr < 4; rr++) {
                mx = fmaxf(mx, red[2048 + (gi*4+rr)*64 + c]);
                mn = fminf(mn, red[3072 + (gi*4+rr)*64 + c]);
            }
            int gp = (rowBase >> 5) + gi;   // global (b*P + p)
            g_max3[(size_t)gp*128 + colBase + c] = mx;
            g_min3[(size_t)gp*128 + colBase + c] = mn;
        }
    }
}

// ---------------- BN finalize ----------------
__global__ void finalize_bn_kernel(const float* __restrict__ g, const float* __restrict__ bt,
                                   int off, int nc) {
    int c = blockIdx.x*blockDim.x + threadIdx.x;
    if (c < nc) {
        double m = g_sum[off+c] * (1.0 / (double)M_ROWS);
        double v = g_sumsq[off+c] * (1.0 / (double)M_ROWS) - m*m;
        float a = g[c] * rsqrtf(fmaxf((float)v, 0.0f) + 1e-5f);
        g_aff_a[off+c] = a;
        g_aff_c[off+c] = (float)((double)bt[c] - m * (double)a);
    }
}

// ---------------- final output: BN3 via max/min-by-sign, layout [B][128][P] ----------------
__global__ void writeout_kernel(float* __restrict__ out) {
    int i = blockIdx.x*256 + threadIdx.x;   // over B*128*P = 1048576
    int p = i & 1023, c = (i >> 10) & 127, b = i >> 17;
    float a = g_aff_a[128 + c], cc = g_aff_c[128 + c];
    float x = (a >= 0.0f) ? g_max3[(size_t)((b<<10)+p)*128 + c]
                          : g_min3[(size_t)((b<<10)+p)*128 + c];
    out[24576 + i] = fmaf(x, a, cc);
}

// ---------------- launch ----------------
extern "C" void kernel_launch(void* const* d_in, const int* in_sizes, int n_in,
                              void* d_out, int out_size) {
    (void)in_sizes; (void)n_in; (void)out_size;
    const float* xyz = (const float*)d_in[0];
    const float* pts = (const float*)d_in[1];
    const float* w1  = (const float*)d_in[2];
    const float* b1  = (const float*)d_in[3];
    const float* g1  = (const float*)d_in[4];
    const float* bt1 = (const float*)d_in[5];
    const float* w2  = (const float*)d_in[6];
    const float* b2  = (const float*)d_in[7];
    const float* g2  = (const float*)d_in[8];
    const float* bt2 = (const float*)d_in[9];
    const float* w3  = (const float*)d_in[10];
    const float* b3  = (const float*)d_in[11];
    const float* g3  = (const float*)d_in[12];
    const float* bt3 = (const float*)d_in[13];
    float* out = (float*)d_out;

    const int knn_smem = 2048*16 + 32*128*4 + 32*128*4;  // 65536
    cudaFuncSetAttribute(knn_kernel, cudaFuncAttributeMaxDynamicSharedMemorySize, knn_smem);
    cudaFuncSetAttribute(conv_kernel<67,1>, cudaFuncAttributeMaxDynamicSharedMemorySize, (67*128 + 67*64)*4);
    cudaFuncSetAttribute(conv_kernel<64,2>, cudaFuncAttributeMaxDynamicSharedMemorySize, 49152);
    cudaFuncSetAttribute(conv_kernel<64,3>, cudaFuncAttributeMaxDynamicSharedMemorySize, 49152);

    zero_stats_kernel<<<1, 256>>>();
    transpose_pts_kernel<<<(BB*NN_PTS)/256, 256>>>(pts);
    make_xyz4_kernel<<<(BB*NN_PTS)/256, 256>>>(xyz);
    fps_kernel<<<BB, 1024>>>(out);
    knn_kernel<<<dim3(PP/128, BB), 128, knn_smem>>>();
    conv_kernel<67,1><<<dim3(M_ROWS/128, 1), 128, (67*128 + 67*64)*4>>>(w1, b1);
    finalize_bn_kernel<<<1, 64>>>(g1, bt1, 0, 64);
    conv_kernel<64,2><<<dim3(M_ROWS/128, 1), 128, 49152>>>(w2, b2);
    finalize_bn_kernel<<<1, 64>>>(g2, bt2, 64, 64);
    conv_kernel<64,3><<<dim3(M_ROWS/128, 2), 128, 49152>>>(w3, b3);
    finalize_bn_kernel<<<1, 128>>>(g3, bt3, 128, 128);
    writeout_kernel<<<(BB*128*PP)/256, 256>>>(out);
}

// round 7
// speedup vs baseline: 1.1773x; 1.0287x over previous
#include <cuda_runtime.h>
#include <cfloat>
#include <math.h>

#define BB 8
#define NN_PTS 8192
#define CIN 64
#define PP 1024
#define SS 32
#define M_ROWS (BB*PP*SS)   // 262144

typedef unsigned long long u64;
typedef unsigned int u32;

// ---------------- packed f32x2 helpers (each lane = exact scalar fp32 op) ----------------
__device__ __forceinline__ u64 f2_pack(float a, float b) {
    u64 r; asm("mov.b64 %0, {%1, %2};" : "=l"(r) : "f"(a), "f"(b)); return r;
}
__device__ __forceinline__ void f2_unpack(float& a, float& b, u64 v) {
    asm("mov.b64 {%0, %1}, %2;" : "=f"(a), "=f"(b) : "l"(v));
}
__device__ __forceinline__ u64 f2_add(u64 a, u64 b) {
    u64 r; asm("add.rn.f32x2 %0, %1, %2;" : "=l"(r) : "l"(a), "l"(b)); return r;
}
__device__ __forceinline__ u64 f2_mul(u64 a, u64 b) {
    u64 r; asm("mul.rn.f32x2 %0, %1, %2;" : "=l"(r) : "l"(a), "l"(b)); return r;
}
__device__ __forceinline__ u64 f2_fma(u64 a, u64 b, u64 c) {
    u64 r; asm("fma.rn.f32x2 %0, %1, %2, %3;" : "=l"(r) : "l"(a), "l"(b), "l"(c)); return r;
}

// ---------------- scratch (device globals; no allocations) ----------------
__device__ float  g_pts_t[BB*NN_PTS*CIN];     // 16MB  [b][n][64]
__device__ float4 g_xyz4[BB*NN_PTS];          // [b][n] (x,y,z,|x|^2)
__device__ float4 g_newxyz4[BB*PP];
__device__ int    g_knn[BB*PP*SS];
__device__ float  g_h1[(size_t)M_ROWS*64];    // 64MB
__device__ float  g_h2[(size_t)M_ROWS*64];    // 64MB
__device__ float  g_max3[BB*PP*128];
__device__ float  g_min3[BB*PP*128];
__device__ double g_sum[256];
__device__ double g_sumsq[256];
__device__ float  g_aff_a[256];
__device__ float  g_aff_c[256];

// points [B][64][N] -> g_pts_t [B][N][64]
__global__ void transpose_pts_kernel(const float* __restrict__ pts) {
    int n = blockIdx.x * blockDim.x + threadIdx.x;
    if (n >= BB*NN_PTS) return;
    int b = n >> 13, nn = n & (NN_PTS-1);
    const float* src = pts + (size_t)b*64*NN_PTS + nn;
    float4* dst = reinterpret_cast<float4*>(g_pts_t + (size_t)n*64);
    #pragma unroll
    for (int c4 = 0; c4 < 16; c4++) {
        float4 v;
        v.x = src[(size_t)(c4*4+0)*NN_PTS];
        v.y = src[(size_t)(c4*4+1)*NN_PTS];
        v.z = src[(size_t)(c4*4+2)*NN_PTS];
        v.w = src[(size_t)(c4*4+3)*NN_PTS];
        dst[c4] = v;
    }
}

// xyz [B][3][N] -> g_xyz4 [B][N] with precomputed |x|^2
// FMA-contracted square-reduce: fma(z,z, fma(y,y, x*x)) — matches reference emitter (BIT-EXACT, do not change)
// Also zeroes BN stats (block 0).
__global__ void make_xyz4_kernel(const float* __restrict__ xyz) {
    int i = blockIdx.x * blockDim.x + threadIdx.x;
    if (blockIdx.x == 0 && threadIdx.x < 256) {
        g_sum[threadIdx.x] = 0.0; g_sumsq[threadIdx.x] = 0.0;
    }
    if (i >= BB*NN_PTS) return;
    int b = i >> 13, nn = i & (NN_PTS-1);
    float x = xyz[((size_t)b*3+0)*NN_PTS + nn];
    float y = xyz[((size_t)b*3+1)*NN_PTS + nn];
    float z = xyz[((size_t)b*3+2)*NN_PTS + nn];
    float x2 = __fmaf_rn(z, z, __fmaf_rn(y, y, __fmul_rn(x, x)));
    g_xyz4[i] = make_float4(x, y, z, x2);
}

// ---------------- FPS: 1 block per batch, 1024 threads ----------------
// All points staged in smem (centroid load = LDS not LDG-L2); one barrier per
// iteration (parity double-buffered per-warp results + redundant final reduce
// in every warp); REDUX hi/lo argmax with strict-greater + first-index ties.
// Distance math bit-identical to reference: (p-c) then fma(dz,dz,fma(dy,dy,dx*dx)).
__global__ void __launch_bounds__(1024, 1) fps_kernel(float* __restrict__ d_out) {
    extern __shared__ char sm_fps[];
    float4* Xs = reinterpret_cast<float4*>(sm_fps);                  // 8192 float4 = 128KB
    u64*    swv = reinterpret_cast<u64*>(sm_fps + NN_PTS*16);        // [2][32]

    const int b = blockIdx.x;
    const int tid = threadIdx.x;
    const int lane = tid & 31, wrp = tid >> 5;
    const float4* X = g_xyz4 + (size_t)b*NN_PTS;

    u64 px2[4], py2[4], pz2[4];
    float dist[8];
    #pragma unroll
    for (int pr = 0; pr < 4; pr++) {
        float4 v0 = X[tid*8 + 2*pr];
        float4 v1 = X[tid*8 + 2*pr + 1];
        Xs[tid*8 + 2*pr]   = v0;
        Xs[tid*8 + 2*pr+1] = v1;
        px2[pr] = f2_pack(v0.x, v1.x);
        py2[pr] = f2_pack(v0.y, v1.y);
        pz2[pr] = f2_pack(v0.z, v1.z);
        dist[2*pr] = 1e10f; dist[2*pr+1] = 1e10f;
    }
    __syncthreads();

    int far = 0;
    for (int it = 0; it < PP; it++) {
        float4 c = Xs[far];   // LDS broadcast (29 cyc vs L2 ~234)
        if (tid == 0) {
            g_newxyz4[b*PP + it] = c;
            d_out[((size_t)b*3+0)*PP + it] = c.x;
            d_out[((size_t)b*3+1)*PP + it] = c.y;
            d_out[((size_t)b*3+2)*PP + it] = c.z;
        }
        // (p - c) computed as p + (-c): negation exact, per-lane rounding identical
        u64 ncx = f2_pack(-c.x, -c.x);
        u64 ncy = f2_pack(-c.y, -c.y);
        u64 ncz = f2_pack(-c.z, -c.z);

        float bestv = -1.0f; int besti = 0;
        #pragma unroll
        for (int pr = 0; pr < 4; pr++) {
            u64 dx = f2_add(px2[pr], ncx);
            u64 dy = f2_add(py2[pr], ncy);
            u64 dz = f2_add(pz2[pr], ncz);
            u64 s  = f2_fma(dz, dz, f2_fma(dy, dy, f2_mul(dx, dx)));
            float d0, d1; f2_unpack(d0, d1, s);
            dist[2*pr] = fminf(dist[2*pr], d0);
            if (dist[2*pr] > bestv)   { bestv = dist[2*pr];   besti = tid*8 + 2*pr; }
            dist[2*pr+1] = fminf(dist[2*pr+1], d1);
            if (dist[2*pr+1] > bestv) { bestv = dist[2*pr+1]; besti = tid*8 + 2*pr + 1; }
        }

        // warp argmax: uint order == float order (nonneg); ties -> smallest index
        u32 hi  = __float_as_uint(bestv);
        u32 mhi = __reduce_max_sync(0xffffffffu, hi);
        u32 lo  = (hi == mhi) ? (u32)(8191 - besti) : 0u;
        u32 mlo = __reduce_max_sync(0xffffffffu, lo);
        if (lane == 0) swv[(it & 1)*32 + wrp] = ((u64)mhi << 32) | mlo;
        __syncthreads();
        // redundant block-level reduce in EVERY warp (no second barrier)
        u64 w = swv[(it & 1)*32 + lane];
        u32 hi2 = (u32)(w >> 32);
        u32 m2  = __reduce_max_sync(0xffffffffu, hi2);
        u32 lo2 = (hi2 == m2) ? (u32)w : 0u;
        u32 ml2 = __reduce_max_sync(0xffffffffu, lo2);
        far = 8191 - (int)ml2;
    }
}

// ---------------- KNN: thread per centroid, shared xyz tiles (BIT-EXACT selection math) ----
__global__ void knn_kernel() {
    extern __shared__ char sm_raw[];
    float4* tile = reinterpret_cast<float4*>(sm_raw);                 // 2048 float4 = 32KB
    float*  lv   = reinterpret_cast<float*>(sm_raw + 2048*16);        // [32][128] = 16KB
    int*    li   = reinterpret_cast<int*>(sm_raw + 2048*16 + 32*128*4); // 16KB

    const int b = blockIdx.y;
    const int tid = threadIdx.x;
    const int p = blockIdx.x*128 + tid;

    float4 q = g_newxyz4[b*PP + p];
    const float p2 = q.w;

    #pragma unroll
    for (int s = 0; s < SS; s++) { lv[s*128+tid] = FLT_MAX; li[s*128+tid] = 0x7fffffff; }
    float worst = FLT_MAX; int wslot = 0; int widx = 0x7fffffff;

    const float4* X = g_xyz4 + (size_t)b*NN_PTS;
    for (int t0 = 0; t0 < NN_PTS; t0 += 2048) {
        __syncthreads();
        for (int j = tid; j < 2048; j += 128) tile[j] = X[t0 + j];
        __syncthreads();
        #pragma unroll 4
        for (int j = 0; j < 2048; j++) {
            float4 v = tile[j];
            float dot = __fmaf_rn(q.z, v.z, __fmaf_rn(q.y, v.y, __fmul_rn(q.x, v.x)));
            float d2 = __fadd_rn(__fsub_rn(p2, __fmul_rn(2.0f, dot)), v.w);
            if (d2 < worst || (d2 == worst && (t0 + j) < widx)) {
                lv[wslot*128+tid] = d2; li[wslot*128+tid] = t0 + j;
                float mw = -FLT_MAX; int ms = 0; int mi = -1;
                #pragma unroll
                for (int s = 0; s < SS; s++) {
                    float vv = lv[s*128+tid]; int ii = li[s*128+tid];
                    if (vv > mw || (vv == mw && ii > mi)) { mw = vv; ms = s; mi = ii; }
                }
                worst = mw; wslot = ms; widx = mi;
            }
        }
    }
    #pragma unroll
    for (int s = 0; s < SS; s++) g_knn[((size_t)(b*PP + p))*SS + s] = li[s*128+tid];
}

// ---------------- conv layers: 128x64 block tile, 8x8 thread tile, f32x2 mainloop --------
// Exact fp32; per-output single-accumulator ascending-k FMA chain (bit-identical to scalar).
template<int K, int LAYER>
__global__ void conv_kernel(const float* __restrict__ W, const float* __restrict__ bias) {
    extern __shared__ float sm[];
    float* A_s = sm;              // [K][128]
    float* W_s = sm + K*128;      // [K][64]
    const int tid = threadIdx.x;
    const int rowBase = blockIdx.x * 128;
    const int colBase = blockIdx.y * 64;

    for (int i = tid; i < K*64; i += 128) {
        int k = i >> 6, o = i & 63;
        W_s[i] = W[(size_t)(colBase + o)*K + k];
    }
    {
        int r = rowBase + tid;
        if constexpr (LAYER == 1) {
            int b = r >> 15, rem = r & 32767, p = rem >> 5;
            int idx = g_knn[r];
            float4 nq = g_newxyz4[(b<<10) + p];
            float4 g  = g_xyz4[(b<<13) + idx];
            A_s[0*128+tid] = __fsub_rn(g.x, nq.x);
            A_s[1*128+tid] = __fsub_rn(g.y, nq.y);
            A_s[2*128+tid] = __fsub_rn(g.z, nq.z);
            const float4* prow = reinterpret_cast<const float4*>(g_pts_t + ((size_t)(b<<13) + idx)*64);
            #pragma unroll
            for (int c4 = 0; c4 < 16; c4++) {
                float4 v = prow[c4];
                int c = 3 + c4*4;
                A_s[(c+0)*128+tid] = v.x;
                A_s[(c+1)*128+tid] = v.y;
                A_s[(c+2)*128+tid] = v.z;
                A_s[(c+3)*128+tid] = v.w;
            }
        } else {
            const float* hin = (LAYER == 2) ? g_h1 : g_h2;
            const int off = (LAYER == 2) ? 0 : 64;
            const float4* hrow = reinterpret_cast<const float4*>(hin + (size_t)r*64);
            #pragma unroll
            for (int c4 = 0; c4 < 16; c4++) {
                float4 v = hrow[c4];
                int c = c4*4;
                A_s[(c+0)*128+tid] = fmaxf(fmaf(v.x, g_aff_a[off+c+0], g_aff_c[off+c+0]), 0.0f);
                A_s[(c+1)*128+tid] = fmaxf(fmaf(v.y, g_aff_a[off+c+1], g_aff_c[off+c+1]), 0.0f);
                A_s[(c+2)*128+tid] = fmaxf(fmaf(v.z, g_aff_a[off+c+2], g_aff_c[off+c+2]), 0.0f);
                A_s[(c+3)*128+tid] = fmaxf(fmaf(v.w, g_aff_a[off+c+3], g_aff_c[off+c+3]), 0.0f);
            }
        }
    }
    __syncthreads();

    const int rg = tid >> 3, cg = tid & 7;
    u64 acc2[8][4];
    #pragma unroll
    for (int i = 0; i < 8; i++)
        #pragma unroll
        for (int jj = 0; jj < 4; jj++) acc2[i][jj] = 0ull;   // two packed +0.0f

    #pragma unroll 4
    for (int k = 0; k < K; k++) {
        float4 a0 = *reinterpret_cast<const float4*>(&A_s[k*128 + rg*8]);
        float4 a1 = *reinterpret_cast<const float4*>(&A_s[k*128 + rg*8 + 4]);
        ulonglong2 wA = *reinterpret_cast<const ulonglong2*>(&W_s[k*64 + cg*8]);
        ulonglong2 wB = *reinterpret_cast<const ulonglong2*>(&W_s[k*64 + cg*8 + 4]);
        u64 wv2[4] = {wA.x, wA.y, wB.x, wB.y};
        float av[8] = {a0.x,a0.y,a0.z,a0.w,a1.x,a1.y,a1.z,a1.w};
        #pragma unroll
        for (int i = 0; i < 8; i++) {
            u64 ad = f2_pack(av[i], av[i]);
            #pragma unroll
            for (int jj = 0; jj < 4; jj++)
                acc2[i][jj] = f2_fma(ad, wv2[jj], acc2[i][jj]);
        }
    }

    float acc[8][8];
    #pragma unroll
    for (int i = 0; i < 8; i++)
        #pragma unroll
        for (int jj = 0; jj < 4; jj++)
            f2_unpack(acc[i][2*jj], acc[i][2*jj+1], acc2[i][jj]);

    float bb[8];
    #pragma unroll
    for (int j = 0; j < 8; j++) bb[j] = bias[colBase + cg*8 + j];
    #pragma unroll
    for (int i = 0; i < 8; i++)
        #pragma unroll
        for (int j = 0; j < 8; j++) acc[i][j] = __fadd_rn(acc[i][j], bb[j]);

    float cs[8], cq[8];
    #pragma unroll
    for (int j = 0; j < 8; j++) { cs[j] = 0.0f; cq[j] = 0.0f; }
    #pragma unroll
    for (int i = 0; i < 8; i++)
        #pragma unroll
        for (int j = 0; j < 8; j++) { cs[j] += acc[i][j]; cq[j] += acc[i][j]*acc[i][j]; }

    __syncthreads();   // done reading A_s/W_s — reuse as reduction space
    float* red = A_s;
    #pragma unroll
    for (int j = 0; j < 8; j++) {
        red[rg*64 + cg*8 + j] = cs[j];
        red[1024 + rg*64 + cg*8 + j] = cq[j];
    }
    if constexpr (LAYER == 3) {
        float tmx[8], tmn[8];
        #pragma unroll
        for (int j = 0; j < 8; j++) { tmx[j] = -FLT_MAX; tmn[j] = FLT_MAX; }
        #pragma unroll
        for (int i = 0; i < 8; i++)
            #pragma unroll
            for (int j = 0; j < 8; j++) { tmx[j] = fmaxf(tmx[j], acc[i][j]); tmn[j] = fminf(tmn[j], acc[i][j]); }
        #pragma unroll
        for (int j = 0; j < 8; j++) {
            red[2048 + rg*64 + cg*8 + j] = tmx[j];
            red[3072 + rg*64 + cg*8 + j] = tmn[j];
        }
    }
    __syncthreads();

    if (tid < 64) {
        float s = 0.0f, s2 = 0.0f;
        #pragma unroll
        for (int r2 = 0; r2 < 16; r2++) { s += red[r2*64 + tid]; s2 += red[1024 + r2*64 + tid]; }
        const int statsOff = (LAYER == 1) ? 0 : ((LAYER == 2) ? 64 : 128);
        atomicAdd(&g_sum[statsOff + colBase + tid], (double)s);
        atomicAdd(&g_sumsq[statsOff + colBase + tid], (double)s2);
    }

    if constexpr (LAYER < 3) {
        float* hout = (LAYER == 1) ? g_h1 : g_h2;
        #pragma unroll
        for (int i = 0; i < 8; i++) {
            float4 v0 = make_float4(acc[i][0], acc[i][1], acc[i][2], acc[i][3]);
            float4 v1 = make_float4(acc[i][4], acc[i][5], acc[i][6], acc[i][7]);
            float4* dst = reinterpret_cast<float4*>(hout + (size_t)(rowBase + rg*8 + i)*64 + cg*8);
            dst[0] = v0; dst[1] = v1;
        }
    } else {
        #pragma unroll
        for (int t = 0; t < 2; t++) {
            int o = tid*2 + t;
            int gi = o >> 6, c = o & 63;
            float mx = -FLT_MAX, mn = FLT_MAX;
            #pragma unroll
            for (int rr = 0; rr < 4; rr++) {
                mx = fmaxf(mx, red[2048 + (gi*4+rr)*64 + c]);
                mn = fminf(mn, red[3072 + (gi*4+rr)*64 + c]);
            }
            int gp = (rowBase >> 5) + gi;   // global (b*P + p)
            g_max3[(size_t)gp*128 + colBase + c] = mx;
            g_min3[(size_t)gp*128 + colBase + c] = mn;
        }
    }
}

// ---------------- BN finalize ----------------
__global__ void finalize_bn_kernel(const float* __restrict__ g, const float* __restrict__ bt,
                                   int off, int nc) {
    int c = blockIdx.x*blockDim.x + threadIdx.x;
    if (c < nc) {
        double m = g_sum[off+c] * (1.0 / (double)M_ROWS);
        double v = g_sumsq[off+c] * (1.0 / (double)M_ROWS) - m*m;
        float a = g[c] * rsqrtf(fmaxf((float)v, 0.0f) + 1e-5f);
        g_aff_a[off+c] = a;
        g_aff_c[off+c] = (float)((double)bt[c] - m * (double)a);
    }
}

// ---------------- final output: BN3 via max/min-by-sign, layout [B][128][P] ----------------
__global__ void writeout_kernel(float* __restrict__ out) {
    int i = blockIdx.x*256 + threadIdx.x;   // over B*128*P = 1048576
    int p = i & 1023, c = (i >> 10) & 127, b = i >> 17;
    float a = g_aff_a[128 + c], cc = g_aff_c[128 + c];
    float x = (a >= 0.0f) ? g_max3[(size_t)((b<<10)+p)*128 + c]
                          : g_min3[(size_t)((b<<10)+p)*128 + c];
    out[24576 + i] = fmaf(x, a, cc);
}

// ---------------- launch ----------------
extern "C" void kernel_launch(void* const* d_in, const int* in_sizes, int n_in,
                              void* d_out, int out_size) {
    (void)in_sizes; (void)n_in; (void)out_size;
    const float* xyz = (const float*)d_in[0];
    const float* pts = (const float*)d_in[1];
    const float* w1  = (const float*)d_in[2];
    const float* b1  = (const float*)d_in[3];
    const float* g1  = (const float*)d_in[4];
    const float* bt1 = (const float*)d_in[5];
    const float* w2  = (const float*)d_in[6];
    const float* b2  = (const float*)d_in[7];
    const float* g2  = (const float*)d_in[8];
    const float* bt2 = (const float*)d_in[9];
    const float* w3  = (const float*)d_in[10];
    const float* b3  = (const float*)d_in[11];
    const float* g3  = (const float*)d_in[12];
    const float* bt3 = (const float*)d_in[13];
    float* out = (float*)d_out;

    const int fps_smem = NN_PTS*16 + 2*32*8;             // 131584
    const int knn_smem = 2048*16 + 32*128*4 + 32*128*4;  // 65536
    cudaFuncSetAttribute(fps_kernel, cudaFuncAttributeMaxDynamicSharedMemorySize, fps_smem);
    cudaFuncSetAttribute(knn_kernel, cudaFuncAttributeMaxDynamicSharedMemorySize, knn_smem);
    cudaFuncSetAttribute(conv_kernel<67,1>, cudaFuncAttributeMaxDynamicSharedMemorySize, (67*128 + 67*64)*4);
    cudaFuncSetAttribute(conv_kernel<64,2>, cudaFuncAttributeMaxDynamicSharedMemorySize, 49152);
    cudaFuncSetAttribute(conv_kernel<64,3>, cudaFuncAttributeMaxDynamicSharedMemorySize, 49152);

    transpose_pts_kernel<<<(BB*NN_PTS)/256, 256>>>(pts);
    make_xyz4_kernel<<<(BB*NN_PTS)/256, 256>>>(xyz);
    fps_kernel<<<BB, 1024, fps_smem>>>(out);
    knn_kernel<<<dim3(PP/128, BB), 128, knn_smem>>>();
    conv_kernel<67,1><<<dim3(M_ROWS/128, 1), 128, (67*128 + 67*64)*4>>>(w1, b1);
    finalize_bn_kernel<<<1, 64>>>(g1, bt1, 0, 64);
    conv_kernel<64,2><<<dim3(M_ROWS/128, 1), 128, 49152>>>(w2, b2);
    finalize_bn_kernel<<<1, 64>>>(g2, bt2, 64, 64);
    conv_kernel<64,3><<<dim3(M_ROWS/128, 2), 128, 49152>>>(w3, b3);
    finalize_bn_kernel<<<1, 128>>>(g3, bt3, 128, 128);
    writeout_kernel<<<(BB*128*PP)/256, 256>>>(out);
}